// round 2
// baseline (speedup 1.0000x reference)
#include <cuda_runtime.h>

#define C 512
#define NMAX 50000

// ---------------- scratch (no allocation allowed) ----------------
__device__ float g_sU[(size_t)NMAX * C];
__device__ float g_sI[(size_t)NMAX * C];
__device__ float g_cntU[NMAX];
__device__ float g_cntI[NMAX];
__device__ float g_outU[(size_t)NMAX * C];
__device__ float g_outI[(size_t)NMAX * C];
__device__ float g_xu[(size_t)NMAX * C];
__device__ float g_xi[(size_t)NMAX * C];

// ---------------- scatter: s[dst] += x[src], cnt[dst] += 1 ----------------
// 128 threads per edge (one float4 per thread), 2 edges per 256-thread block.
__global__ void scatter_kernel(const float* __restrict__ xsrc,
                               const int* __restrict__ edge, int E,
                               float* __restrict__ s, float* __restrict__ cnt) {
    int e = blockIdx.x * 2 + (threadIdx.x >> 7);
    int lane = threadIdx.x & 127;
    if (e >= E) return;
    int src = edge[e];
    int dst = edge[E + e];
    const float4* xs = reinterpret_cast<const float4*>(xsrc) + (size_t)src * (C / 4);
    float4* sd = reinterpret_cast<float4*>(s) + (size_t)dst * (C / 4);
    float4 v = xs[lane];
    atomicAdd(sd + lane, v);   // sm_90+: vector red.global.add.v4.f32
    if (lane == 0) atomicAdd(cnt + dst, 1.0f);
}

// ---------------- fused GEMM ----------------
// Out[m, o] = sum_k S[m,k]*Wl0[o,k] + (S[m,k]*inv[m])*Wl1[o,k]
//           + X[m,k]*(Wr0[o,k]+Wr1[o,k])  + B0[o] + B1[o]
#define BM 128
#define BN 128
#define BK 8

__global__ __launch_bounds__(256, 2)
void gemm_fused(const float* __restrict__ S, const float* __restrict__ cnt,
                const float* __restrict__ X,
                const float* __restrict__ Wl0, const float* __restrict__ Wl1,
                const float* __restrict__ Wr0, const float* __restrict__ Wr1,
                const float* __restrict__ B0, const float* __restrict__ B1,
                float* __restrict__ Out, int M) {
    __shared__ float As[BK][BM];
    __shared__ float Bs[BK][BN];
    int tid = threadIdx.x;
    int m0 = blockIdx.y * BM;
    int n0 = blockIdx.x * BN;
    int warp = tid >> 5, lane = tid & 31;
    // warp covers 4 row-threads x 8 col-threads -> smem reads: 4*32B + 8*32B per k-step
    int ty = (warp >> 1) * 4 + (lane >> 3);   // 0..15 (thread row, 8 output rows each)
    int tx = (warp & 1) * 8 + (lane & 7);     // 0..15 (thread col, 8 output cols each)

    int a_row = tid >> 1;           // 0..127
    int a_k = (tid & 1) * 4;        // 0 or 4
    int gm = m0 + a_row;
    bool a_ok = gm < M;
    float inv = 1.0f;
    if (a_ok) inv = 1.0f / fmaxf(cnt[gm], 1.0f);

    float acc[8][8];
#pragma unroll
    for (int i = 0; i < 8; i++)
#pragma unroll
        for (int j = 0; j < 8; j++) acc[i][j] = 0.0f;

    for (int seg = 0; seg < 3; ++seg) {
        const float* Ap = (seg == 2 ? X : S);
        float ascale = (seg == 1 ? inv : 1.0f);
        const float* Wp = (seg == 0 ? Wl0 : (seg == 1 ? Wl1 : Wr0));

        for (int k0 = 0; k0 < C; k0 += BK) {
            float4 av = make_float4(0.f, 0.f, 0.f, 0.f);
            if (a_ok) av = *reinterpret_cast<const float4*>(Ap + (size_t)gm * C + k0 + a_k);
            As[a_k + 0][a_row] = av.x * ascale;
            As[a_k + 1][a_row] = av.y * ascale;
            As[a_k + 2][a_row] = av.z * ascale;
            As[a_k + 3][a_row] = av.w * ascale;

            float4 bv = *reinterpret_cast<const float4*>(Wp + (size_t)(n0 + a_row) * C + k0 + a_k);
            if (seg == 2) {
                float4 b2 = *reinterpret_cast<const float4*>(Wr1 + (size_t)(n0 + a_row) * C + k0 + a_k);
                bv.x += b2.x; bv.y += b2.y; bv.z += b2.z; bv.w += b2.w;
            }
            Bs[a_k + 0][a_row] = bv.x;
            Bs[a_k + 1][a_row] = bv.y;
            Bs[a_k + 2][a_row] = bv.z;
            Bs[a_k + 3][a_row] = bv.w;
            __syncthreads();

#pragma unroll
            for (int kk = 0; kk < BK; ++kk) {
                float ar[8], br[8];
                *(float4*)&ar[0] = *(const float4*)&As[kk][ty * 8];
                *(float4*)&ar[4] = *(const float4*)&As[kk][ty * 8 + 4];
                *(float4*)&br[0] = *(const float4*)&Bs[kk][tx * 8];
                *(float4*)&br[4] = *(const float4*)&Bs[kk][tx * 8 + 4];
#pragma unroll
                for (int i = 0; i < 8; i++)
#pragma unroll
                    for (int j = 0; j < 8; j++) acc[i][j] += ar[i] * br[j];
            }
            __syncthreads();
        }
    }

    // epilogue: bias + store
#pragma unroll
    for (int i = 0; i < 8; i++) {
        int m = m0 + ty * 8 + i;
        if (m >= M) continue;
#pragma unroll
        for (int j = 0; j < 8; j += 4) {
            int n = n0 + tx * 8 + j;
            float4 o;
            o.x = acc[i][j + 0] + B0[n + 0] + B1[n + 0];
            o.y = acc[i][j + 1] + B0[n + 1] + B1[n + 1];
            o.z = acc[i][j + 2] + B0[n + 2] + B1[n + 2];
            o.w = acc[i][j + 3] + B0[n + 3] + B1[n + 3];
            *reinterpret_cast<float4*>(Out + (size_t)m * C + n) = o;
        }
    }
}

// ---------------- LayerNorm + ReLU (one row per block, 128 threads) -------
__global__ void ln_relu_kernel(const float* __restrict__ in,
                               const float* __restrict__ g,
                               const float* __restrict__ b,
                               float* __restrict__ out, int M) {
    int row = blockIdx.x;
    if (row >= M) return;
    int t = threadIdx.x;  // 0..127, one float4 each
    float4 v = reinterpret_cast<const float4*>(in + (size_t)row * C)[t];
    float sum = v.x + v.y + v.z + v.w;
    float sq = v.x * v.x + v.y * v.y + v.z * v.z + v.w * v.w;
#pragma unroll
    for (int o = 16; o; o >>= 1) {
        sum += __shfl_xor_sync(0xffffffffu, sum, o);
        sq  += __shfl_xor_sync(0xffffffffu, sq, o);
    }
    __shared__ float ssum[4], ssq[4];
    int w = t >> 5;
    if ((t & 31) == 0) { ssum[w] = sum; ssq[w] = sq; }
    __syncthreads();
    sum = ssum[0] + ssum[1] + ssum[2] + ssum[3];
    sq  = ssq[0] + ssq[1] + ssq[2] + ssq[3];
    float mu = sum * (1.0f / C);
    float var = sq * (1.0f / C) - mu * mu;
    float rstd = rsqrtf(var + 1e-5f);
    float4 gv = reinterpret_cast<const float4*>(g)[t];
    float4 bv = reinterpret_cast<const float4*>(b)[t];
    float4 o;
    o.x = fmaxf(gv.x * (v.x - mu) * rstd + bv.x, 0.0f);
    o.y = fmaxf(gv.y * (v.y - mu) * rstd + bv.y, 0.0f);
    o.z = fmaxf(gv.z * (v.z - mu) * rstd + bv.z, 0.0f);
    o.w = fmaxf(gv.w * (v.w - mu) * rstd + bv.w, 0.0f);
    reinterpret_cast<float4*>(out + (size_t)row * C)[t] = o;
}

// ---------------- host launch ----------------
#define WOFF(l, e, a) (((size_t)((l) * 2 + (e)) * 2 + (a)) * C * C)
#define BOFF(l, e, a) (((size_t)((l) * 2 + (e)) * 2 + (a)) * C)

extern "C" void kernel_launch(void* const* d_in, const int* in_sizes, int n_in,
                              void* d_out, int out_size) {
    const float* x_user = (const float*)d_in[0];
    const float* x_item = (const float*)d_in[1];
    const float* Wl     = (const float*)d_in[2];
    const float* bl     = (const float*)d_in[3];
    const float* Wr     = (const float*)d_in[4];
    const float* ln_g   = (const float*)d_in[5];
    const float* ln_b   = (const float*)d_in[6];
    const int* edge_ui  = (const int*)d_in[7];
    const int* edge_iu  = (const int*)d_in[8];

    int Nu = in_sizes[0] / C;
    int Ni = in_sizes[1] / C;
    int E  = in_sizes[7] / 2;

    float *sU, *sI, *cU, *cI, *oU, *oI, *xu, *xi;
    cudaGetSymbolAddress((void**)&sU, g_sU);
    cudaGetSymbolAddress((void**)&sI, g_sI);
    cudaGetSymbolAddress((void**)&cU, g_cntU);
    cudaGetSymbolAddress((void**)&cI, g_cntI);
    cudaGetSymbolAddress((void**)&oU, g_outU);
    cudaGetSymbolAddress((void**)&oI, g_outI);
    cudaGetSymbolAddress((void**)&xu, g_xu);
    cudaGetSymbolAddress((void**)&xi, g_xi);

    float* out_u = (float*)d_out;
    float* out_i = (float*)d_out + (size_t)Nu * C;

    const float* cu_x = x_user;
    const float* ci_x = x_item;

    for (int l = 0; l < 2; ++l) {
        cudaMemsetAsync(sI, 0, (size_t)Ni * C * sizeof(float), 0);
        cudaMemsetAsync(cI, 0, (size_t)Ni * sizeof(float), 0);
        cudaMemsetAsync(sU, 0, (size_t)Nu * C * sizeof(float), 0);
        cudaMemsetAsync(cU, 0, (size_t)Nu * sizeof(float), 0);

        scatter_kernel<<<(E + 1) / 2, 256>>>(cu_x, edge_ui, E, sI, cI);  // user->item
        scatter_kernel<<<(E + 1) / 2, 256>>>(ci_x, edge_iu, E, sU, cU);  // item->user

        gemm_fused<<<dim3(C / BN, (Ni + BM - 1) / BM), 256>>>(
            sI, cI, ci_x,
            Wl + WOFF(l, 0, 0), Wl + WOFF(l, 0, 1),
            Wr + WOFF(l, 0, 0), Wr + WOFF(l, 0, 1),
            bl + BOFF(l, 0, 0), bl + BOFF(l, 0, 1), oI, Ni);

        gemm_fused<<<dim3(C / BN, (Nu + BM - 1) / BM), 256>>>(
            sU, cU, cu_x,
            Wl + WOFF(l, 1, 0), Wl + WOFF(l, 1, 1),
            Wr + WOFF(l, 1, 0), Wr + WOFF(l, 1, 1),
            bl + BOFF(l, 1, 0), bl + BOFF(l, 1, 1), oU, Nu);

        float* du = (l == 1) ? out_u : xu;
        float* di = (l == 1) ? out_i : xi;
        ln_relu_kernel<<<Nu, 128>>>(oU, ln_g + (size_t)(l * 2 + 0) * C,
                                    ln_b + (size_t)(l * 2 + 0) * C, du, Nu);
        ln_relu_kernel<<<Ni, 128>>>(oI, ln_g + (size_t)(l * 2 + 1) * C,
                                    ln_b + (size_t)(l * 2 + 1) * C, di, Ni);
        cu_x = du;
        ci_x = di;
    }
}

// round 4
// speedup vs baseline: 2.0638x; 2.0638x over previous
#include <cuda_runtime.h>

#define C 512
#define NMAX 50000

// ---------------- scratch (no allocation allowed) ----------------
__device__ float g_sU[(size_t)NMAX * C];
__device__ float g_sI[(size_t)NMAX * C];
__device__ float g_cntU[NMAX];
__device__ float g_cntI[NMAX];
__device__ float g_outU[(size_t)NMAX * C];
__device__ float g_outI[(size_t)NMAX * C];
__device__ float g_xu[(size_t)NMAX * C];
__device__ float g_xi[(size_t)NMAX * C];

// ---------------- scatter: s[dst] += x[src], cnt[dst] += 1 ----------------
__global__ void scatter_kernel(const float* __restrict__ xsrc,
                               const int* __restrict__ edge, int E,
                               float* __restrict__ s, float* __restrict__ cnt) {
    int e = blockIdx.x * 2 + (threadIdx.x >> 7);
    int lane = threadIdx.x & 127;
    if (e >= E) return;
    int src = edge[e];
    int dst = edge[E + e];
    const float4* xs = reinterpret_cast<const float4*>(xsrc) + (size_t)src * (C / 4);
    float4* sd = reinterpret_cast<float4*>(s) + (size_t)dst * (C / 4);
    float4 v = xs[lane];
    atomicAdd(sd + lane, v);
    if (lane == 0) atomicAdd(cnt + dst, 1.0f);
}

// ---------------- tf32 tensor-core fused GEMM ----------------
// Out[m,n] = inv[m]*(S@Wl1^T) + S@Wl0^T + X@(Wr0+Wr1)^T + B0[n] + B1[n]
#define BM 128
#define BN 128
#define BK 16
#define APAD 20   // row stride (floats) in smem; conflict-free for frag LDS

__device__ __forceinline__ unsigned f2tf(float f) {
    unsigned r;
    asm("cvt.rna.tf32.f32 %0, %1;" : "=r"(r) : "f"(f));
    return r;
}

__device__ __forceinline__ void mma_tf32(float* d, const unsigned* a, const unsigned* b) {
    asm volatile(
        "mma.sync.aligned.m16n8k8.row.col.f32.tf32.tf32.f32 "
        "{%0,%1,%2,%3}, {%4,%5,%6,%7}, {%8,%9}, {%0,%1,%2,%3};\n"
        : "+f"(d[0]), "+f"(d[1]), "+f"(d[2]), "+f"(d[3])
        : "r"(a[0]), "r"(a[1]), "r"(a[2]), "r"(a[3]), "r"(b[0]), "r"(b[1]));
}

__global__ __launch_bounds__(256, 2)
void gemm_fused(const float* __restrict__ S, const float* __restrict__ cnt,
                const float* __restrict__ X,
                const float* __restrict__ Wl0, const float* __restrict__ Wl1,
                const float* __restrict__ Wr0, const float* __restrict__ Wr1,
                const float* __restrict__ B0, const float* __restrict__ B1,
                float* __restrict__ Out, int M) {
    __shared__ unsigned As[BM * APAD];
    __shared__ unsigned Bs[BN * APAD];

    int tid = threadIdx.x;
    int m0 = blockIdx.y * BM;
    int n0 = blockIdx.x * BN;
    int warp = tid >> 5, lane = tid & 31;
    int wr = warp >> 2;        // 0..1 : warp row (64 rows each)
    int wc = warp & 3;         // 0..3 : warp col (32 cols each)
    int g = lane >> 2;         // 0..7
    int tg = lane & 3;         // 0..3

    // per-thread inv (for the mean segment), per mfrag: rows base+g, base+g+8
    float invlo[4], invhi[4];
#pragma unroll
    for (int i = 0; i < 4; i++) {
        int r0 = m0 + wr * 64 + i * 16 + g;
        int r1 = r0 + 8;
        invlo[i] = (r0 < M) ? 1.0f / fmaxf(cnt[r0], 1.0f) : 1.0f;
        invhi[i] = (r1 < M) ? 1.0f / fmaxf(cnt[r1], 1.0f) : 1.0f;
    }

    float acc[4][4][4];
#pragma unroll
    for (int i = 0; i < 4; i++)
#pragma unroll
        for (int j = 0; j < 4; j++)
#pragma unroll
            for (int q = 0; q < 4; q++) acc[i][j][q] = 0.0f;

    const int NIT = 96;  // 3 segments * (512/16)
    uint4 ra[2], rb[2];

    // tile load into registers (with tf32 rounding)
    auto ldg_tile = [&](int it) {
        int phase = it >> 5;                 // 0: S@Wl1, 1: S@Wl0, 2: X@(Wr0+Wr1)
        int k0 = (it & 31) * BK;
        const float* Ap = (phase < 2) ? S : X;
        const float* Bp = (phase == 0) ? Wl1 : (phase == 1 ? Wl0 : Wr0);
#pragma unroll
        for (int h = 0; h < 2; ++h) {
            int slot = tid + h * 256;
            int r = slot >> 2, c4 = slot & 3;
            int gm = m0 + r;
            float4 av = make_float4(0.f, 0.f, 0.f, 0.f);
            if (gm < M)
                av = *reinterpret_cast<const float4*>(Ap + (size_t)gm * C + k0 + c4 * 4);
            ra[h].x = f2tf(av.x); ra[h].y = f2tf(av.y);
            ra[h].z = f2tf(av.z); ra[h].w = f2tf(av.w);
            float4 bv = *reinterpret_cast<const float4*>(Bp + (size_t)(n0 + r) * C + k0 + c4 * 4);
            if (phase == 2) {
                float4 b2 = *reinterpret_cast<const float4*>(Wr1 + (size_t)(n0 + r) * C + k0 + c4 * 4);
                bv.x += b2.x; bv.y += b2.y; bv.z += b2.z; bv.w += b2.w;
            }
            rb[h].x = f2tf(bv.x); rb[h].y = f2tf(bv.y);
            rb[h].z = f2tf(bv.z); rb[h].w = f2tf(bv.w);
        }
    };

    ldg_tile(0);

    for (int it = 0; it < NIT; ++it) {
#pragma unroll
        for (int h = 0; h < 2; ++h) {
            int slot = tid + h * 256;
            int r = slot >> 2, c4 = slot & 3;
            *reinterpret_cast<uint4*>(&As[r * APAD + c4 * 4]) = ra[h];
            *reinterpret_cast<uint4*>(&Bs[r * APAD + c4 * 4]) = rb[h];
        }
        __syncthreads();
        if (it + 1 < NIT) ldg_tile(it + 1);

#pragma unroll
        for (int kk = 0; kk < BK; kk += 8) {
            unsigned a[4][4], b[4][2];
#pragma unroll
            for (int i = 0; i < 4; i++) {
                int row = wr * 64 + i * 16 + g;
                a[i][0] = As[row * APAD + kk + tg];
                a[i][1] = As[(row + 8) * APAD + kk + tg];
                a[i][2] = As[row * APAD + kk + tg + 4];
                a[i][3] = As[(row + 8) * APAD + kk + tg + 4];
            }
#pragma unroll
            for (int j = 0; j < 4; j++) {
                int col = wc * 32 + j * 8 + g;
                b[j][0] = Bs[col * APAD + kk + tg];
                b[j][1] = Bs[col * APAD + kk + tg + 4];
            }
#pragma unroll
            for (int i = 0; i < 4; i++)
#pragma unroll
                for (int j = 0; j < 4; j++) mma_tf32(acc[i][j], a[i], b[j]);
        }

        if (it == 31) {
            // mean segment done: scale by 1/cnt
#pragma unroll
            for (int i = 0; i < 4; i++)
#pragma unroll
                for (int j = 0; j < 4; j++) {
                    acc[i][j][0] *= invlo[i];
                    acc[i][j][1] *= invlo[i];
                    acc[i][j][2] *= invhi[i];
                    acc[i][j][3] *= invhi[i];
                }
        }
        __syncthreads();
    }

    // epilogue: bias + store
#pragma unroll
    for (int i = 0; i < 4; i++) {
        int r0 = m0 + wr * 64 + i * 16 + g;
        int r1 = r0 + 8;
#pragma unroll
        for (int j = 0; j < 4; j++) {
            int n = n0 + wc * 32 + j * 8 + tg * 2;
            float bias0 = B0[n] + B1[n];
            float bias1 = B0[n + 1] + B1[n + 1];
            if (r0 < M) {
                float2 o = make_float2(acc[i][j][0] + bias0, acc[i][j][1] + bias1);
                *reinterpret_cast<float2*>(Out + (size_t)r0 * C + n) = o;
            }
            if (r1 < M) {
                float2 o = make_float2(acc[i][j][2] + bias0, acc[i][j][3] + bias1);
                *reinterpret_cast<float2*>(Out + (size_t)r1 * C + n) = o;
            }
        }
    }
}

// ---------------- LayerNorm + ReLU ----------------
__global__ void ln_relu_kernel(const float* __restrict__ in,
                               const float* __restrict__ g,
                               const float* __restrict__ b,
                               float* __restrict__ out, int M) {
    int row = blockIdx.x;
    if (row >= M) return;
    int t = threadIdx.x;
    float4 v = reinterpret_cast<const float4*>(in + (size_t)row * C)[t];
    float sum = v.x + v.y + v.z + v.w;
    float sq = v.x * v.x + v.y * v.y + v.z * v.z + v.w * v.w;
#pragma unroll
    for (int o = 16; o; o >>= 1) {
        sum += __shfl_xor_sync(0xffffffffu, sum, o);
        sq  += __shfl_xor_sync(0xffffffffu, sq, o);
    }
    __shared__ float ssum[4], ssq[4];
    int w = t >> 5;
    if ((t & 31) == 0) { ssum[w] = sum; ssq[w] = sq; }
    __syncthreads();
    sum = ssum[0] + ssum[1] + ssum[2] + ssum[3];
    sq  = ssq[0] + ssq[1] + ssq[2] + ssq[3];
    float mu = sum * (1.0f / C);
    float var = sq * (1.0f / C) - mu * mu;
    float rstd = rsqrtf(var + 1e-5f);
    float4 gv = reinterpret_cast<const float4*>(g)[t];
    float4 bv = reinterpret_cast<const float4*>(b)[t];
    float4 o;
    o.x = fmaxf(gv.x * (v.x - mu) * rstd + bv.x, 0.0f);
    o.y = fmaxf(gv.y * (v.y - mu) * rstd + bv.y, 0.0f);
    o.z = fmaxf(gv.z * (v.z - mu) * rstd + bv.z, 0.0f);
    o.w = fmaxf(gv.w * (v.w - mu) * rstd + bv.w, 0.0f);
    reinterpret_cast<float4*>(out + (size_t)row * C)[t] = o;
}

// ---------------- host launch ----------------
#define WOFF(l, e, a) (((size_t)((l) * 2 + (e)) * 2 + (a)) * C * C)
#define BOFF(l, e, a) (((size_t)((l) * 2 + (e)) * 2 + (a)) * C)

extern "C" void kernel_launch(void* const* d_in, const int* in_sizes, int n_in,
                              void* d_out, int out_size) {
    const float* x_user = (const float*)d_in[0];
    const float* x_item = (const float*)d_in[1];
    const float* Wl     = (const float*)d_in[2];
    const float* bl     = (const float*)d_in[3];
    const float* Wr     = (const float*)d_in[4];
    const float* ln_g   = (const float*)d_in[5];
    const float* ln_b   = (const float*)d_in[6];
    const int* edge_ui  = (const int*)d_in[7];
    const int* edge_iu  = (const int*)d_in[8];

    int Nu = in_sizes[0] / C;
    int Ni = in_sizes[1] / C;
    int E  = in_sizes[7] / 2;

    float *sU, *sI, *cU, *cI, *oU, *oI, *xu, *xi;
    cudaGetSymbolAddress((void**)&sU, g_sU);
    cudaGetSymbolAddress((void**)&sI, g_sI);
    cudaGetSymbolAddress((void**)&cU, g_cntU);
    cudaGetSymbolAddress((void**)&cI, g_cntI);
    cudaGetSymbolAddress((void**)&oU, g_outU);
    cudaGetSymbolAddress((void**)&oI, g_outI);
    cudaGetSymbolAddress((void**)&xu, g_xu);
    cudaGetSymbolAddress((void**)&xi, g_xi);

    float* out_u = (float*)d_out;
    float* out_i = (float*)d_out + (size_t)Nu * C;

    const float* cu_x = x_user;
    const float* ci_x = x_item;

    for (int l = 0; l < 2; ++l) {
        cudaMemsetAsync(sI, 0, (size_t)Ni * C * sizeof(float), 0);
        cudaMemsetAsync(cI, 0, (size_t)Ni * sizeof(float), 0);
        cudaMemsetAsync(sU, 0, (size_t)Nu * C * sizeof(float), 0);
        cudaMemsetAsync(cU, 0, (size_t)Nu * sizeof(float), 0);

        scatter_kernel<<<(E + 1) / 2, 256>>>(cu_x, edge_ui, E, sI, cI);  // user->item
        scatter_kernel<<<(E + 1) / 2, 256>>>(ci_x, edge_iu, E, sU, cU);  // item->user

        gemm_fused<<<dim3(C / BN, (Ni + BM - 1) / BM), 256>>>(
            sI, cI, ci_x,
            Wl + WOFF(l, 0, 0), Wl + WOFF(l, 0, 1),
            Wr + WOFF(l, 0, 0), Wr + WOFF(l, 0, 1),
            bl + BOFF(l, 0, 0), bl + BOFF(l, 0, 1), oI, Ni);

        gemm_fused<<<dim3(C / BN, (Nu + BM - 1) / BM), 256>>>(
            sU, cU, cu_x,
            Wl + WOFF(l, 1, 0), Wl + WOFF(l, 1, 1),
            Wr + WOFF(l, 1, 0), Wr + WOFF(l, 1, 1),
            bl + BOFF(l, 1, 0), bl + BOFF(l, 1, 1), oU, Nu);

        float* du = (l == 1) ? out_u : xu;
        float* di = (l == 1) ? out_i : xi;
        ln_relu_kernel<<<Nu, 128>>>(oU, ln_g + (size_t)(l * 2 + 0) * C,
                                    ln_b + (size_t)(l * 2 + 0) * C, du, Nu);
        ln_relu_kernel<<<Ni, 128>>>(oI, ln_g + (size_t)(l * 2 + 1) * C,
                                    ln_b + (size_t)(l * 2 + 1) * C, di, Ni);
        cu_x = du;
        ci_x = di;
    }
}

// round 6
// speedup vs baseline: 2.2026x; 1.0672x over previous
#include <cuda_runtime.h>
#include <cstdint>

#define C 512
#define NMAX 50000

// ---------------- scratch (no allocation allowed) ----------------
__device__ float g_sU[(size_t)NMAX * C];
__device__ float g_sI[(size_t)NMAX * C];
__device__ float g_cntU[NMAX];
__device__ float g_cntI[NMAX];
__device__ float g_outU[(size_t)NMAX * C];
__device__ float g_outI[(size_t)NMAX * C];
__device__ float g_xu[(size_t)NMAX * C];
__device__ float g_xi[(size_t)NMAX * C];

// ---------------- scatter: s[dst] += x[src], cnt[dst] += 1 ----------------
__global__ void scatter_kernel(const float* __restrict__ xsrc,
                               const int* __restrict__ edge, int E,
                               float* __restrict__ s, float* __restrict__ cnt) {
    int e = blockIdx.x * 2 + (threadIdx.x >> 7);
    int lane = threadIdx.x & 127;
    if (e >= E) return;
    int src = edge[e];
    int dst = edge[E + e];
    const float4* xs = reinterpret_cast<const float4*>(xsrc) + (size_t)src * (C / 4);
    float4* sd = reinterpret_cast<float4*>(s) + (size_t)dst * (C / 4);
    float4 v = xs[lane];
    atomicAdd(sd + lane, v);
    if (lane == 0) atomicAdd(cnt + dst, 1.0f);
}

// ---------------- tf32 tensor-core fused GEMM (ldmatrix fragments) -------
// Out[m,n] = S@Wl0^T + inv[m]*(S@Wl1^T) + X@(Wr0+Wr1)^T + B0[n] + B1[n]
#define BM 128
#define BN 128
#define BK 16
#define STRIDE 20   // floats per smem row (80B): 16B-aligned, LDSM conflict-free

__device__ __forceinline__ unsigned smem_u32(const void* p) {
    unsigned a;
    asm("{ .reg .u64 t; cvta.to.shared.u64 t, %1; cvt.u32.u64 %0, t; }" : "=r"(a) : "l"(p));
    return a;
}
__device__ __forceinline__ unsigned f2tf(float f) {
    unsigned r;
    asm("cvt.rna.tf32.f32 %0, %1;" : "=r"(r) : "f"(f));
    return r;
}
__device__ __forceinline__ void mma_tf32(float* d, const unsigned* a, const unsigned* b) {
    asm volatile(
        "mma.sync.aligned.m16n8k8.row.col.f32.tf32.tf32.f32 "
        "{%0,%1,%2,%3}, {%4,%5,%6,%7}, {%8,%9}, {%0,%1,%2,%3};\n"
        : "+f"(d[0]), "+f"(d[1]), "+f"(d[2]), "+f"(d[3])
        : "r"(a[0]), "r"(a[1]), "r"(a[2]), "r"(a[3]), "r"(b[0]), "r"(b[1]));
}
#define LDSM_X4(r0, r1, r2, r3, addr) \
    asm volatile("ldmatrix.sync.aligned.m8n8.x4.shared.b16 {%0,%1,%2,%3}, [%4];" \
                 : "=r"(r0), "=r"(r1), "=r"(r2), "=r"(r3) : "r"(addr))

__global__ __launch_bounds__(256, 2)
void gemm_fused(const float* __restrict__ S, const float* __restrict__ cnt,
                const float* __restrict__ X,
                const float* __restrict__ Wl0, const float* __restrict__ Wl1,
                const float* __restrict__ Wr0, const float* __restrict__ Wr1,
                const float* __restrict__ B0, const float* __restrict__ B1,
                float* __restrict__ Out, int M) {
    __shared__ unsigned As[BM * STRIDE];
    __shared__ unsigned Bs[BN * STRIDE];

    int tid = threadIdx.x;
    int m0 = blockIdx.y * BM;
    int n0 = blockIdx.x * BN;
    int warp = tid >> 5, lane = tid & 31;
    int wr = warp >> 2;        // 0..1 : warp row (64 rows each)
    int wc = warp & 3;         // 0..3 : warp col (32 cols each)
    int g = lane >> 2;         // 0..7
    int tg = lane & 3;         // 0..3

    // ldmatrix per-lane base addresses (sel = lane/8 picks the 4 sub-matrices)
    int sel = lane >> 3, l8 = lane & 7;
    unsigned aBase = smem_u32(As) +
        (unsigned)(((wr * 64 + (sel & 1) * 8 + l8) * STRIDE + (sel >> 1) * 4) * 4);
    unsigned bBase = smem_u32(Bs) +
        (unsigned)(((wc * 32 + (sel >> 1) * 8 + l8) * STRIDE + (sel & 1) * 4) * 4);

    // per-thread inv (for the mean segment)
    float invlo[4], invhi[4];
#pragma unroll
    for (int i = 0; i < 4; i++) {
        int r0 = m0 + wr * 64 + i * 16 + g;
        int r1 = r0 + 8;
        invlo[i] = (r0 < M) ? 1.0f / fmaxf(cnt[r0], 1.0f) : 1.0f;
        invhi[i] = (r1 < M) ? 1.0f / fmaxf(cnt[r1], 1.0f) : 1.0f;
    }

    float acc[4][4][4];
#pragma unroll
    for (int i = 0; i < 4; i++)
#pragma unroll
        for (int j = 0; j < 4; j++)
#pragma unroll
            for (int q = 0; q < 4; q++) acc[i][j][q] = 0.0f;

    const int NIT = 96;  // 3 segments * (512/16)
    uint4 ra[2], rb[2];

    // tile load into registers (with tf32 rounding)
    auto ldg_tile = [&](int it) {
        int phase = it >> 5;                 // 0: S@Wl1, 1: S@Wl0, 2: X@(Wr0+Wr1)
        int k0 = (it & 31) * BK;
        const float* Ap = (phase < 2) ? S : X;
        const float* Bp = (phase == 0) ? Wl1 : (phase == 1 ? Wl0 : Wr0);
#pragma unroll
        for (int h = 0; h < 2; ++h) {
            int slot = tid + h * 256;
            int r = slot >> 2, c4 = slot & 3;
            int gm = m0 + r;
            float4 av = make_float4(0.f, 0.f, 0.f, 0.f);
            if (gm < M)
                av = *reinterpret_cast<const float4*>(Ap + (size_t)gm * C + k0 + c4 * 4);
            ra[h].x = f2tf(av.x); ra[h].y = f2tf(av.y);
            ra[h].z = f2tf(av.z); ra[h].w = f2tf(av.w);
            float4 bv = *reinterpret_cast<const float4*>(Bp + (size_t)(n0 + r) * C + k0 + c4 * 4);
            if (phase == 2) {
                float4 b2 = *reinterpret_cast<const float4*>(Wr1 + (size_t)(n0 + r) * C + k0 + c4 * 4);
                bv.x += b2.x; bv.y += b2.y; bv.z += b2.z; bv.w += b2.w;
            }
            rb[h].x = f2tf(bv.x); rb[h].y = f2tf(bv.y);
            rb[h].z = f2tf(bv.z); rb[h].w = f2tf(bv.w);
        }
    };

    ldg_tile(0);

    for (int it = 0; it < NIT; ++it) {
#pragma unroll
        for (int h = 0; h < 2; ++h) {
            int slot = tid + h * 256;
            int r = slot >> 2, c4 = slot & 3;
            *reinterpret_cast<uint4*>(&As[r * STRIDE + c4 * 4]) = ra[h];
            *reinterpret_cast<uint4*>(&Bs[r * STRIDE + c4 * 4]) = rb[h];
        }
        __syncthreads();
        if (it + 1 < NIT) ldg_tile(it + 1);

#pragma unroll
        for (int kk2 = 0; kk2 < 2; ++kk2) {         // k8-step: kk = kk2*8
            unsigned koff = kk2 * 32;               // (kk/4)*16 bytes
            unsigned a[4][4], b[4][2];
#pragma unroll
            for (int i = 0; i < 4; i++) {
                LDSM_X4(a[i][0], a[i][1], a[i][2], a[i][3],
                        aBase + (unsigned)(i * 16 * STRIDE * 4) + koff);
            }
#pragma unroll
            for (int p = 0; p < 2; p++) {
                LDSM_X4(b[2 * p][0], b[2 * p][1], b[2 * p + 1][0], b[2 * p + 1][1],
                        bBase + (unsigned)(p * 16 * STRIDE * 4) + koff);
            }
#pragma unroll
            for (int i = 0; i < 4; i++)
#pragma unroll
                for (int j = 0; j < 4; j++) mma_tf32(acc[i][j], a[i], b[j]);
        }

        if (it == 31) {
            // mean segment done: scale by 1/cnt
#pragma unroll
            for (int i = 0; i < 4; i++)
#pragma unroll
                for (int j = 0; j < 4; j++) {
                    acc[i][j][0] *= invlo[i];
                    acc[i][j][1] *= invlo[i];
                    acc[i][j][2] *= invhi[i];
                    acc[i][j][3] *= invhi[i];
                }
        }
        __syncthreads();
    }

    // epilogue: bias + store
#pragma unroll
    for (int i = 0; i < 4; i++) {
        int r0 = m0 + wr * 64 + i * 16 + g;
        int r1 = r0 + 8;
#pragma unroll
        for (int j = 0; j < 4; j++) {
            int n = n0 + wc * 32 + j * 8 + tg * 2;
            float bias0 = B0[n] + B1[n];
            float bias1 = B0[n + 1] + B1[n + 1];
            if (r0 < M) {
                float2 o = make_float2(acc[i][j][0] + bias0, acc[i][j][1] + bias1);
                *reinterpret_cast<float2*>(Out + (size_t)r0 * C + n) = o;
            }
            if (r1 < M) {
                float2 o = make_float2(acc[i][j][2] + bias0, acc[i][j][3] + bias1);
                *reinterpret_cast<float2*>(Out + (size_t)r1 * C + n) = o;
            }
        }
    }
}

// ---------------- LayerNorm + ReLU ----------------
__global__ void ln_relu_kernel(const float* __restrict__ in,
                               const float* __restrict__ g,
                               const float* __restrict__ b,
                               float* __restrict__ out, int M) {
    int row = blockIdx.x;
    if (row >= M) return;
    int t = threadIdx.x;
    float4 v = reinterpret_cast<const float4*>(in + (size_t)row * C)[t];
    float sum = v.x + v.y + v.z + v.w;
    float sq = v.x * v.x + v.y * v.y + v.z * v.z + v.w * v.w;
#pragma unroll
    for (int o = 16; o; o >>= 1) {
        sum += __shfl_xor_sync(0xffffffffu, sum, o);
        sq  += __shfl_xor_sync(0xffffffffu, sq, o);
    }
    __shared__ float ssum[4], ssq[4];
    int w = t >> 5;
    if ((t & 31) == 0) { ssum[w] = sum; ssq[w] = sq; }
    __syncthreads();
    sum = ssum[0] + ssum[1] + ssum[2] + ssum[3];
    sq  = ssq[0] + ssq[1] + ssq[2] + ssq[3];
    float mu = sum * (1.0f / C);
    float var = sq * (1.0f / C) - mu * mu;
    float rstd = rsqrtf(var + 1e-5f);
    float4 gv = reinterpret_cast<const float4*>(g)[t];
    float4 bv = reinterpret_cast<const float4*>(b)[t];
    float4 o;
    o.x = fmaxf(gv.x * (v.x - mu) * rstd + bv.x, 0.0f);
    o.y = fmaxf(gv.y * (v.y - mu) * rstd + bv.y, 0.0f);
    o.z = fmaxf(gv.z * (v.z - mu) * rstd + bv.z, 0.0f);
    o.w = fmaxf(gv.w * (v.w - mu) * rstd + bv.w, 0.0f);
    reinterpret_cast<float4*>(out + (size_t)row * C)[t] = o;
}

// ---------------- host launch ----------------
#define WOFF(l, e, a) (((size_t)((l) * 2 + (e)) * 2 + (a)) * C * C)
#define BOFF(l, e, a) (((size_t)((l) * 2 + (e)) * 2 + (a)) * C)

extern "C" void kernel_launch(void* const* d_in, const int* in_sizes, int n_in,
                              void* d_out, int out_size) {
    const float* x_user = (const float*)d_in[0];
    const float* x_item = (const float*)d_in[1];
    const float* Wl     = (const float*)d_in[2];
    const float* bl     = (const float*)d_in[3];
    const float* Wr     = (const float*)d_in[4];
    const float* ln_g   = (const float*)d_in[5];
    const float* ln_b   = (const float*)d_in[6];
    const int* edge_ui  = (const int*)d_in[7];
    const int* edge_iu  = (const int*)d_in[8];

    int Nu = in_sizes[0] / C;
    int Ni = in_sizes[1] / C;
    int E  = in_sizes[7] / 2;

    float *sU, *sI, *cU, *cI, *oU, *oI, *xu, *xi;
    cudaGetSymbolAddress((void**)&sU, g_sU);
    cudaGetSymbolAddress((void**)&sI, g_sI);
    cudaGetSymbolAddress((void**)&cU, g_cntU);
    cudaGetSymbolAddress((void**)&cI, g_cntI);
    cudaGetSymbolAddress((void**)&oU, g_outU);
    cudaGetSymbolAddress((void**)&oI, g_outI);
    cudaGetSymbolAddress((void**)&xu, g_xu);
    cudaGetSymbolAddress((void**)&xi, g_xi);

    float* out_u = (float*)d_out;
    float* out_i = (float*)d_out + (size_t)Nu * C;

    const float* cu_x = x_user;
    const float* ci_x = x_item;

    for (int l = 0; l < 2; ++l) {
        cudaMemsetAsync(sI, 0, (size_t)Ni * C * sizeof(float), 0);
        cudaMemsetAsync(cI, 0, (size_t)Ni * sizeof(float), 0);
        cudaMemsetAsync(sU, 0, (size_t)Nu * C * sizeof(float), 0);
        cudaMemsetAsync(cU, 0, (size_t)Nu * sizeof(float), 0);

        scatter_kernel<<<(E + 1) / 2, 256>>>(cu_x, edge_ui, E, sI, cI);  // user->item
        scatter_kernel<<<(E + 1) / 2, 256>>>(ci_x, edge_iu, E, sU, cU);  // item->user

        gemm_fused<<<dim3(C / BN, (Ni + BM - 1) / BM), 256>>>(
            sI, cI, ci_x,
            Wl + WOFF(l, 0, 0), Wl + WOFF(l, 0, 1),
            Wr + WOFF(l, 0, 0), Wr + WOFF(l, 0, 1),
            bl + BOFF(l, 0, 0), bl + BOFF(l, 0, 1), oI, Ni);

        gemm_fused<<<dim3(C / BN, (Nu + BM - 1) / BM), 256>>>(
            sU, cU, cu_x,
            Wl + WOFF(l, 1, 0), Wl + WOFF(l, 1, 1),
            Wr + WOFF(l, 1, 0), Wr + WOFF(l, 1, 1),
            bl + BOFF(l, 1, 0), bl + BOFF(l, 1, 1), oU, Nu);

        float* du = (l == 1) ? out_u : xu;
        float* di = (l == 1) ? out_i : xi;
        ln_relu_kernel<<<Nu, 128>>>(oU, ln_g + (size_t)(l * 2 + 0) * C,
                                    ln_b + (size_t)(l * 2 + 0) * C, du, Nu);
        ln_relu_kernel<<<Ni, 128>>>(oI, ln_g + (size_t)(l * 2 + 1) * C,
                                    ln_b + (size_t)(l * 2 + 1) * C, di, Ni);
        cu_x = du;
        ci_x = di;
    }
}